// round 12
// baseline (speedup 1.0000x reference)
#include <cuda_runtime.h>
#include <cuda_fp16.h>
#include <cstdint>

#define BB 8
#define SS 4096
#define DD 256
#define NROWS (BB*SS)
#define NEGV  (-1000000000.0f)
#define NSPLIT 8
#define KSPLIT (SS/NSPLIT)   // 512
#define NCH1 (KSPLIT/32)     // 16
#define NCH2 (DD/32)         // 8
#define P1 272
#define P2 80
#define BUFQ1 (32*P1)        // 8704
#define BUF1  (2*BUFQ1)      // 17408  (Ah,Bh) -- g1
#define A2SZ  (128*P2)       // 10240
#define BUF2  (A2SZ + 32*P1) // 18944  -- g2 (A fp16 + B fp16)

// ---- scratch ----
__device__ float  g_inv_b[NROWS];
__device__ float  g_s1p[NSPLIT][BB*DD*DD];
__device__ __half g_s1h[BB*DD*DD];       // fp16 s1_true
__device__ int    g_mask_kind;

// ============================ helpers ============================
__device__ __forceinline__ uint32_t smem_u32(const void* p) {
    uint32_t a;
    asm("{ .reg .u64 t; cvta.to.shared.u64 t, %1; cvt.u32.u64 %0, t; }"
        : "=r"(a) : "l"(p));
    return a;
}
__device__ __forceinline__ void cp16(uint32_t dst, const void* src) {
    asm volatile("cp.async.cg.shared.global [%0], [%1], 16;" :: "r"(dst), "l"(src));
}
__device__ __forceinline__ void cp_commit() {
    asm volatile("cp.async.commit_group;" ::: "memory");
}
template<int N> __device__ __forceinline__ void cp_wait() {
    asm volatile("cp.async.wait_group %0;" :: "n"(N) : "memory");
}
__device__ __forceinline__ void ldsm_x4(uint32_t* r, uint32_t a) {
    asm volatile("ldmatrix.sync.aligned.m8n8.x4.shared.b16 {%0,%1,%2,%3}, [%4];"
        : "=r"(r[0]), "=r"(r[1]), "=r"(r[2]), "=r"(r[3]) : "r"(a));
}
__device__ __forceinline__ void ldsm_x4t(uint32_t* r, uint32_t a) {
    asm volatile("ldmatrix.sync.aligned.m8n8.x4.trans.shared.b16 {%0,%1,%2,%3}, [%4];"
        : "=r"(r[0]), "=r"(r[1]), "=r"(r[2]), "=r"(r[3]) : "r"(a));
}
__device__ __forceinline__ void mma_f16(float* c, const uint32_t* a, const uint32_t* b) {
    asm volatile(
        "mma.sync.aligned.m16n8k16.row.col.f32.f16.f16.f32 "
        "{%0,%1,%2,%3}, {%4,%5,%6,%7}, {%8,%9}, {%0,%1,%2,%3};"
        : "+f"(c[0]), "+f"(c[1]), "+f"(c[2]), "+f"(c[3])
        : "r"(a[0]), "r"(a[1]), "r"(a[2]), "r"(a[3]), "r"(b[0]), "r"(b[1]));
}
__device__ __forceinline__ uint32_t pack_h(float x0, float x1) {
    __half2 hh = __floats2half2_rn(x0, x1);
    return *reinterpret_cast<uint32_t*>(&hh);
}
__device__ __forceinline__ bool is_masked(const void* mask, int row) {
    int kind = g_mask_kind;
    if (kind == 1) return ((const unsigned char*)mask)[row] != 0;
    if (kind == 2) return ((const float*)mask)[row] != 0.0f;
    return ((const int*)mask)[row] != 0;
}

// ============================ Kernel 1: K row norms + (block 0) mask sniff ============================
__global__ void k_knorm(const float* __restrict__ k, const unsigned int* __restrict__ m) {
    if (blockIdx.x == 0) {
        __shared__ int s_u8, s_f;
        if (threadIdx.x == 0) { s_u8 = 0; s_f = 0; }
        __syncthreads();
        for (int i = threadIdx.x; i < 8192; i += 256) {
            unsigned v = m[i];
            if (v == 0x3F800000u)      s_f  = 1;
            else if (v > 1u)           s_u8 = 1;
        }
        __syncthreads();
        if (threadIdx.x == 0) g_mask_kind = s_u8 ? 1 : (s_f ? 2 : 0);
    }
    int row  = blockIdx.x * 8 + (threadIdx.x >> 5);
    int lane = threadIdx.x & 31;
    const float4* k4 = (const float4*)(k + (size_t)row * DD);
    float sb = 0.f;
#pragma unroll
    for (int j = 0; j < 2; j++) {
        float4 b = k4[lane + 32 * j];
        sb += b.x*b.x + b.y*b.y + b.z*b.z + b.w*b.w;
    }
#pragma unroll
    for (int o = 16; o; o >>= 1) sb += __shfl_xor_sync(0xFFFFFFFFu, sb, o);
    if (lane == 0) g_inv_b[row] = 256.0f / sb;
}

// ============================ Kernel 2: GEMM1 (round-8, single-pass fp16, occ 2) ============================
__global__ void __launch_bounds__(256, 2)
k_g1(const float* __restrict__ K, const float* __restrict__ V) {
    extern __shared__ __align__(16) char sm[];
    const uint32_t sb = smem_u32(sm);
    const int tid = threadIdx.x, lane = tid & 31, wid = tid >> 5;
    const int b = blockIdx.z, split = blockIdx.y;
    const int m0 = (blockIdx.x >> 1) * 128, n0 = (blockIdx.x & 1) * 128;
    const float* Kb   = K + (size_t)b * SS * DD;
    const float* Vb   = V + (size_t)b * SS * DD;
    const float* invb = g_inv_b + b * SS;

    const int sl = tid >> 3, q0 = tid & 7;
    const int wm = (wid >> 2) * 64, wn = (wid & 3) * 32;
    const int rowT = (lane & 7) + ((lane >> 4) << 3);
    const int colT = ((lane >> 3) & 1) << 3;
    const int rowB = lane & 15;
    const int colB = (lane >> 4) << 3;

    float acc[4][4][4];
#pragma unroll
    for (int i = 0; i < 4; i++)
#pragma unroll
        for (int j = 0; j < 4; j++)
#pragma unroll
            for (int t = 0; t < 4; t++) acc[i][j][t] = 0.f;

    float4 rk[4], rv[4]; float ib;
    {
        int s = split * KSPLIT + sl;
        const float* kr = Kb + (size_t)s * DD + m0;
        const float* vr = Vb + (size_t)s * DD + n0;
        ib = invb[s];
#pragma unroll
        for (int j = 0; j < 4; j++) {
            rk[j] = *(const float4*)(kr + 4 * (q0 + 8 * j));
            rv[j] = *(const float4*)(vr + 4 * (q0 + 8 * j));
        }
    }
    {
        char* Ah = sm; char* Bh = sm + BUFQ1;
#pragma unroll
        for (int j = 0; j < 4; j++) {
            int off = sl * P1 + 8 * (q0 + 8 * j);
            *(uint2*)(Ah + off) = make_uint2(pack_h(rk[j].x * ib, rk[j].y * ib),
                                             pack_h(rk[j].z * ib, rk[j].w * ib));
            *(uint2*)(Bh + off) = make_uint2(pack_h(rv[j].x, rv[j].y),
                                             pack_h(rv[j].z, rv[j].w));
        }
    }
    __syncthreads();

    for (int c = 0; c < NCH1; c++) {
        if (c + 1 < NCH1) {
            int s = split * KSPLIT + (c + 1) * 32 + sl;
            const float* kr = Kb + (size_t)s * DD + m0;
            const float* vr = Vb + (size_t)s * DD + n0;
            ib = invb[s];
#pragma unroll
            for (int j = 0; j < 4; j++) {
                rk[j] = *(const float4*)(kr + 4 * (q0 + 8 * j));
                rv[j] = *(const float4*)(vr + 4 * (q0 + 8 * j));
            }
        }
        const uint32_t ub = sb + (uint32_t)(c & 1) * BUF1;
        const uint32_t uAh = ub, uBh = ub + BUFQ1;
#pragma unroll
        for (int ks = 0; ks < 32; ks += 16) {
            uint32_t ah[4][4], bh[4][2];
#pragma unroll
            for (int mf = 0; mf < 4; mf++) {
                uint32_t a = (uint32_t)((ks + rowT) * P1 + 2 * (wm + mf * 16 + colT));
                ldsm_x4t(ah[mf], uAh + a);
            }
#pragma unroll
            for (int nb = 0; nb < 2; nb++) {
                uint32_t a = (uint32_t)((ks + rowB) * P1 + 2 * (wn + nb * 16 + colB));
                ldsm_x4t(&bh[nb * 2][0], uBh + a);
            }
#pragma unroll
            for (int mi = 0; mi < 4; mi++)
#pragma unroll
                for (int ni = 0; ni < 4; ni++)
                    mma_f16(acc[mi][ni], ah[mi], bh[ni]);
        }
        if (c + 1 < NCH1) {
            char* bp = sm + ((c + 1) & 1) * BUF1;
            char* Ah = bp; char* Bh = bp + BUFQ1;
#pragma unroll
            for (int j = 0; j < 4; j++) {
                int off = sl * P1 + 8 * (q0 + 8 * j);
                *(uint2*)(Ah + off) = make_uint2(pack_h(rk[j].x * ib, rk[j].y * ib),
                                                 pack_h(rk[j].z * ib, rk[j].w * ib));
                *(uint2*)(Bh + off) = make_uint2(pack_h(rv[j].x, rv[j].y),
                                                 pack_h(rv[j].z, rv[j].w));
            }
        }
        __syncthreads();
    }

    float* out = g_s1p[split] + (size_t)b * DD * DD;
    const int r0 = lane >> 2, cp = (lane & 3) * 2;
#pragma unroll
    for (int mi = 0; mi < 4; mi++)
#pragma unroll
        for (int ni = 0; ni < 4; ni++) {
            int m = m0 + wm + mi * 16 + r0;
            int n = n0 + wn + ni * 8 + cp;
            *(float2*)(out + (size_t)m * DD + n)       = make_float2(acc[mi][ni][0], acc[mi][ni][1]);
            *(float2*)(out + (size_t)(m + 8) * DD + n) = make_float2(acc[mi][ni][2], acc[mi][ni][3]);
        }
}

// ============================ Kernel 3: reduce 8 partials -> fp16 s1_true ============================
__global__ void k_reduce() {   // grid (32 dchunks, 8 b), 256 thr (e)
    const int b = blockIdx.y, dc = blockIdx.x, e = threadIdx.x;
    const float r = 1.0f / 256.0f;
    size_t base = ((size_t)b * DD + dc * 8) * DD + e;
#pragma unroll
    for (int d8 = 0; d8 < 8; d8++) {
        size_t idx = base + (size_t)d8 * DD;
        float s = 0.f;
#pragma unroll
        for (int p = 0; p < NSPLIT; p++) s += g_s1p[p][idx];
        g_s1h[idx] = __float2half(s * r);   // s1_true
    }
}

// ============================ Kernel 4: GEMM2 (r8 geometry; B via cp.async fp16) ============================
__global__ void __launch_bounds__(256, 2)
k_g2(const float* __restrict__ Q, const void* __restrict__ mask,
     float* __restrict__ Out) {
    extern __shared__ __align__(16) char sm[];
    const uint32_t sb = smem_u32(sm);
    const int tid = threadIdx.x, lane = tid & 31, wid = tid >> 5;
    const int b = blockIdx.z, m0 = blockIdx.y * 128, n0 = blockIdx.x * 128;
    const float* Qb  = Q + (size_t)b * SS * DD;
    const char* S1B  = (const char*)(g_s1h + (size_t)b * DD * DD);
    float* smul = (float*)(sm + 3 * BUF2);

    const int ar = tid >> 1, aq0 = tid & 1;    // A: 2 thr/row, 128 rows
    const int br = tid >> 4, bc = tid & 15;    // B cp.async: 16 thr/row, rows br, br+16
    const int wm = (wid >> 2) * 64, wn = (wid & 3) * 32;
    const int rowA = lane & 15, colA = (lane >> 4) << 3;
    const int rowB = lane & 15, colB = (lane >> 4) << 3;

    float acc[4][4][4];
#pragma unroll
    for (int i = 0; i < 4; i++)
#pragma unroll
        for (int j = 0; j < 4; j++)
#pragma unroll
            for (int t = 0; t < 4; t++) acc[i][j][t] = 0.f;

    const bool msk = is_masked(mask, b * SS + m0 + ar);
    float qss = 0.f;
    float4 ra[4];

    auto issueB = [&](int cc, int bi) {
#pragma unroll
        for (int t = 0; t < 2; t++) {
            int r = br + t * 16;
            cp16(sb + bi * BUF2 + A2SZ + r * P1 + bc * 16,
                 S1B + ((size_t)(cc * 32 + r) * DD + n0 + bc * 8) * 2);
        }
        cp_commit();
    };
    auto ldA = [&](int cc) {
        const float* qr = Qb + (size_t)(m0 + ar) * DD + cc * 32;
#pragma unroll
        for (int j = 0; j < 4; j++) {
            ra[j] = *(const float4*)(qr + 4 * (aq0 + 2 * j));
            qss += ra[j].x*ra[j].x + ra[j].y*ra[j].y + ra[j].z*ra[j].z + ra[j].w*ra[j].w;
            if (msk) ra[j] = make_float4(1.f, 1.f, 1.f, 1.f);
        }
    };
    auto stA = [&](int bi) {
        char* Ah = sm + bi * BUF2;
#pragma unroll
        for (int j = 0; j < 4; j++) {
            int off = ar * P2 + 8 * (aq0 + 2 * j);
            *(uint2*)(Ah + off) = make_uint2(pack_h(ra[j].x, ra[j].y),
                                             pack_h(ra[j].z, ra[j].w));
        }
    };

    // prologue: chunks 0,1 staged
    issueB(0, 0); issueB(1, 1);
    ldA(0); stA(0); ldA(1); stA(1);
    cp_wait<1>();          // B(0) complete
    __syncthreads();

    for (int c = 0; c < NCH2; c++) {
        if (c + 2 < NCH2) { issueB(c + 2, (c + 2) % 3); ldA(c + 2); }
        const uint32_t ub = sb + (uint32_t)(c % 3) * BUF2;
        const uint32_t uAh = ub, uBh = ub + A2SZ;
#pragma unroll
        for (int ks = 0; ks < 32; ks += 16) {
            uint32_t ah[4][4], bh[4][2];
#pragma unroll
            for (int mf = 0; mf < 4; mf++) {
                uint32_t a = (uint32_t)((wm + mf * 16 + rowA) * P2 + 2 * (ks + colA));
                ldsm_x4(ah[mf], uAh + a);
            }
#pragma unroll
            for (int nb = 0; nb < 2; nb++) {
                uint32_t a = (uint32_t)((ks + rowB) * P1 + 2 * (wn + nb * 16 + colB));
                ldsm_x4t(&bh[nb * 2][0], uBh + a);
            }
#pragma unroll
            for (int mi = 0; mi < 4; mi++)
#pragma unroll
                for (int ni = 0; ni < 4; ni++)
                    mma_f16(acc[mi][ni], ah[mi], bh[ni]);
        }
        if (c + 2 < NCH2) stA((c + 2) % 3);
        if (c + 1 < NCH2) {
            if (c + 2 < NCH2) cp_wait<1>(); else cp_wait<0>();   // B(c+1) done
            __syncthreads();
        }
    }

    qss += __shfl_xor_sync(0xFFFFFFFFu, qss, 1);
    if (aq0 == 0) smul[ar] = msk ? 0.0f : 1.0f / qss;
    __syncthreads();

    const float sc = 1.0f / 256.0f;
    const int r0 = lane >> 2, cp = (lane & 3) * 2;
#pragma unroll
    for (int mi = 0; mi < 4; mi++) {
        int m1 = m0 + wm + mi * 16 + r0;
        int m2 = m1 + 8;
        float mu1 = smul[m1 - m0], mu2 = smul[m2 - m0];
        float s1f = (mu1 == 0.0f) ? (NEGV * sc) : mu1 * sc;
        float s2f = (mu2 == 0.0f) ? (NEGV * sc) : mu2 * sc;
        float* o1 = Out + ((size_t)b * SS + m1) * DD;
        float* o2 = Out + ((size_t)b * SS + m2) * DD;
#pragma unroll
        for (int ni = 0; ni < 4; ni++) {
            int n = n0 + wn + ni * 8 + cp;
            *(float2*)(o1 + n) = make_float2(acc[mi][ni][0] * s1f, acc[mi][ni][1] * s1f);
            *(float2*)(o2 + n) = make_float2(acc[mi][ni][2] * s2f, acc[mi][ni][3] * s2f);
        }
    }
}

// ===========================================================================
extern "C" void kernel_launch(void* const* d_in, const int* in_sizes, int n_in,
                              void* d_out, int out_size) {
    const float* q    = (const float*)d_in[0];
    const float* k    = (const float*)d_in[1];
    const float* v    = (const float*)d_in[2];
    const void*  mask = d_in[3];
    float* out = (float*)d_out;

    const int SMEM_G1 = 2 * BUF1;          // 34816
    const int SMEM_G2 = 3 * BUF2 + 512;    // 57344
    cudaFuncSetAttribute(k_g1, cudaFuncAttributeMaxDynamicSharedMemorySize, SMEM_G1);
    cudaFuncSetAttribute(k_g2, cudaFuncAttributeMaxDynamicSharedMemorySize, SMEM_G2);

    k_knorm<<<NROWS / 8, 256>>>(k, (const unsigned int*)mask);
    k_g1<<<dim3(4, NSPLIT, BB), 256, SMEM_G1>>>(k, v);
    k_reduce<<<dim3(32, 8), 256>>>();
    k_g2<<<dim3(2, SS / 128, BB), 256, SMEM_G2>>>(q, mask, out);
}

// round 14
// speedup vs baseline: 1.4085x; 1.4085x over previous
#include <cuda_runtime.h>
#include <cuda_fp16.h>
#include <cstdint>

#define BB 8
#define SS 4096
#define DD 256
#define NROWS (BB*SS)
#define NEGV  (-1000000000.0f)
#define NSPLIT 8
#define KSPLIT (SS/NSPLIT)   // 512
#define NCH1 (KSPLIT/32)     // 16
#define NCH2 (DD/32)         // 8
#define P1 272
#define P2 80
#define BUFQ1 (32*P1)        // 8704
#define BUF1  (2*BUFQ1)      // 17408  (Ah,Bh) -- g1
#define A2SZ  (128*P2)       // 10240
#define BUF2  (A2SZ + 32*P1) // 18944  -- g2

// ---- scratch ----
__device__ __half g_kh[NROWS*DD];        // fp16 K * 256/||k||^2
__device__ float  g_s1p[NSPLIT][BB*DD*DD];
__device__ __half g_s1h[BB*DD*DD];       // fp16 s1_true
__device__ int    g_mask_kind;

// ============================ helpers ============================
__device__ __forceinline__ uint32_t smem_u32(const void* p) {
    uint32_t a;
    asm("{ .reg .u64 t; cvta.to.shared.u64 t, %1; cvt.u32.u64 %0, t; }"
        : "=r"(a) : "l"(p));
    return a;
}
__device__ __forceinline__ void ldsm_x4(uint32_t* r, uint32_t a) {
    asm volatile("ldmatrix.sync.aligned.m8n8.x4.shared.b16 {%0,%1,%2,%3}, [%4];"
        : "=r"(r[0]), "=r"(r[1]), "=r"(r[2]), "=r"(r[3]) : "r"(a));
}
__device__ __forceinline__ void ldsm_x4t(uint32_t* r, uint32_t a) {
    asm volatile("ldmatrix.sync.aligned.m8n8.x4.trans.shared.b16 {%0,%1,%2,%3}, [%4];"
        : "=r"(r[0]), "=r"(r[1]), "=r"(r[2]), "=r"(r[3]) : "r"(a));
}
__device__ __forceinline__ void mma_f16(float* c, const uint32_t* a, const uint32_t* b) {
    asm volatile(
        "mma.sync.aligned.m16n8k16.row.col.f32.f16.f16.f32 "
        "{%0,%1,%2,%3}, {%4,%5,%6,%7}, {%8,%9}, {%0,%1,%2,%3};"
        : "+f"(c[0]), "+f"(c[1]), "+f"(c[2]), "+f"(c[3])
        : "r"(a[0]), "r"(a[1]), "r"(a[2]), "r"(a[3]), "r"(b[0]), "r"(b[1]));
}
__device__ __forceinline__ uint32_t pack_h(float x0, float x1) {
    __half2 hh = __floats2half2_rn(x0, x1);
    return *reinterpret_cast<uint32_t*>(&hh);
}
__device__ __forceinline__ bool is_masked(const void* mask, int row) {
    int kind = g_mask_kind;
    if (kind == 1) return ((const unsigned char*)mask)[row] != 0;
    if (kind == 2) return ((const float*)mask)[row] != 0.0f;
    return ((const int*)mask)[row] != 0;
}

// ============================ Kernel 1: K norms -> Kh fp16; (block 0) mask sniff ============================
__global__ void k_knorm(const float* __restrict__ k, const unsigned int* __restrict__ m) {
    if (blockIdx.x == 0) {
        __shared__ int s_u8, s_f;
        if (threadIdx.x == 0) { s_u8 = 0; s_f = 0; }
        __syncthreads();
        for (int i = threadIdx.x; i < 8192; i += 256) {
            unsigned v = m[i];
            if (v == 0x3F800000u)      s_f  = 1;
            else if (v > 1u)           s_u8 = 1;
        }
        __syncthreads();
        if (threadIdx.x == 0) g_mask_kind = s_u8 ? 1 : (s_f ? 2 : 0);
    }
    int row  = blockIdx.x * 8 + (threadIdx.x >> 5);
    int lane = threadIdx.x & 31;
    const float4* k4 = (const float4*)(k + (size_t)row * DD);
    float4 b0 = k4[lane], b1 = k4[lane + 32];
    float sb = b0.x*b0.x + b0.y*b0.y + b0.z*b0.z + b0.w*b0.w
             + b1.x*b1.x + b1.y*b1.y + b1.z*b1.z + b1.w*b1.w;
#pragma unroll
    for (int o = 16; o; o >>= 1) sb += __shfl_xor_sync(0xFFFFFFFFu, sb, o);
    const float ib = 256.0f / sb;
    __half* kh = g_kh + (size_t)row * DD;
    *(uint2*)(kh + lane * 4)       = make_uint2(pack_h(b0.x*ib, b0.y*ib), pack_h(b0.z*ib, b0.w*ib));
    *(uint2*)(kh + 128 + lane * 4) = make_uint2(pack_h(b1.x*ib, b1.y*ib), pack_h(b1.z*ib, b1.w*ib));
}

// ============================ Kernel 2: GEMM1 (r8 pipeline; A = precomputed fp16) ============================
__global__ void __launch_bounds__(256, 2)
k_g1(const float* __restrict__ V) {
    extern __shared__ __align__(16) char sm[];
    const uint32_t sb = smem_u32(sm);
    const int tid = threadIdx.x, lane = tid & 31, wid = tid >> 5;
    const int b = blockIdx.z, split = blockIdx.y;
    const int m0 = (blockIdx.x >> 1) * 128, n0 = (blockIdx.x & 1) * 128;
    const __half* KhB = g_kh + (size_t)b * SS * DD;
    const float*  Vb  = V + (size_t)b * SS * DD;

    const int sl = tid >> 3, q0 = tid & 7;
    const int wm = (wid >> 2) * 64, wn = (wid & 3) * 32;
    const int rowT = (lane & 7) + ((lane >> 4) << 3);
    const int colT = ((lane >> 3) & 1) << 3;
    const int rowB = lane & 15;
    const int colB = (lane >> 4) << 3;

    float acc[4][4][4];
#pragma unroll
    for (int i = 0; i < 4; i++)
#pragma unroll
        for (int j = 0; j < 4; j++)
#pragma unroll
            for (int t = 0; t < 4; t++) acc[i][j][t] = 0.f;

    uint2 ra[4]; float4 rv[4];
    {
        int s = split * KSPLIT + sl;
        const __half* kr = KhB + (size_t)s * DD + m0;
        const float*  vr = Vb + (size_t)s * DD + n0;
#pragma unroll
        for (int j = 0; j < 4; j++) {
            ra[j] = *(const uint2*)(kr + 4 * (q0 + 8 * j));
            rv[j] = *(const float4*)(vr + 4 * (q0 + 8 * j));
        }
    }
    {
        char* Ah = sm; char* Bh = sm + BUFQ1;
#pragma unroll
        for (int j = 0; j < 4; j++) {
            int off = sl * P1 + 8 * (q0 + 8 * j);
            *(uint2*)(Ah + off) = ra[j];
            *(uint2*)(Bh + off) = make_uint2(pack_h(rv[j].x, rv[j].y),
                                             pack_h(rv[j].z, rv[j].w));
        }
    }
    __syncthreads();

    for (int c = 0; c < NCH1; c++) {
        if (c + 1 < NCH1) {
            int s = split * KSPLIT + (c + 1) * 32 + sl;
            const __half* kr = KhB + (size_t)s * DD + m0;
            const float*  vr = Vb + (size_t)s * DD + n0;
#pragma unroll
            for (int j = 0; j < 4; j++) {
                ra[j] = *(const uint2*)(kr + 4 * (q0 + 8 * j));
                rv[j] = *(const float4*)(vr + 4 * (q0 + 8 * j));
            }
        }
        const uint32_t ub = sb + (uint32_t)(c & 1) * BUF1;
        const uint32_t uAh = ub, uBh = ub + BUFQ1;
#pragma unroll
        for (int ks = 0; ks < 32; ks += 16) {
            uint32_t ah[4][4], bh[4][2];
#pragma unroll
            for (int mf = 0; mf < 4; mf++) {
                uint32_t a = (uint32_t)((ks + rowT) * P1 + 2 * (wm + mf * 16 + colT));
                ldsm_x4t(ah[mf], uAh + a);
            }
#pragma unroll
            for (int nb = 0; nb < 2; nb++) {
                uint32_t a = (uint32_t)((ks + rowB) * P1 + 2 * (wn + nb * 16 + colB));
                ldsm_x4t(&bh[nb * 2][0], uBh + a);
            }
#pragma unroll
            for (int mi = 0; mi < 4; mi++)
#pragma unroll
                for (int ni = 0; ni < 4; ni++)
                    mma_f16(acc[mi][ni], ah[mi], bh[ni]);
        }
        if (c + 1 < NCH1) {
            char* bp = sm + ((c + 1) & 1) * BUF1;
            char* Ah = bp; char* Bh = bp + BUFQ1;
#pragma unroll
            for (int j = 0; j < 4; j++) {
                int off = sl * P1 + 8 * (q0 + 8 * j);
                *(uint2*)(Ah + off) = ra[j];
                *(uint2*)(Bh + off) = make_uint2(pack_h(rv[j].x, rv[j].y),
                                                 pack_h(rv[j].z, rv[j].w));
            }
        }
        __syncthreads();
    }

    float* out = g_s1p[split] + (size_t)b * DD * DD;
    const int r0 = lane >> 2, cp = (lane & 3) * 2;
#pragma unroll
    for (int mi = 0; mi < 4; mi++)
#pragma unroll
        for (int ni = 0; ni < 4; ni++) {
            int m = m0 + wm + mi * 16 + r0;
            int n = n0 + wn + ni * 8 + cp;
            *(float2*)(out + (size_t)m * DD + n)       = make_float2(acc[mi][ni][0], acc[mi][ni][1]);
            *(float2*)(out + (size_t)(m + 8) * DD + n) = make_float2(acc[mi][ni][2], acc[mi][ni][3]);
        }
}

// ============================ Kernel 3: reduce 8 partials -> fp16 s1_true ============================
__global__ void k_reduce() {   // grid (32 dchunks, 8 b), 256 thr (e)
    const int b = blockIdx.y, dc = blockIdx.x, e = threadIdx.x;
    const float r = 1.0f / 256.0f;
    size_t base = ((size_t)b * DD + dc * 8) * DD + e;
#pragma unroll
    for (int d8 = 0; d8 < 8; d8++) {
        size_t idx = base + (size_t)d8 * DD;
        float s = 0.f;
#pragma unroll
        for (int p = 0; p < NSPLIT; p++) s += g_s1p[p][idx];
        g_s1h[idx] = __float2half(s * r);   // s1_true
    }
}

// ============================ Kernel 4: GEMM2 (r8 pipeline; B = precomputed fp16) ============================
__global__ void __launch_bounds__(256, 2)
k_g2(const float* __restrict__ Q, const void* __restrict__ mask,
     float* __restrict__ Out) {
    extern __shared__ __align__(16) char sm[];
    const uint32_t sb = smem_u32(sm);
    const int tid = threadIdx.x, lane = tid & 31, wid = tid >> 5;
    const int b = blockIdx.z, m0 = blockIdx.y * 128, n0 = blockIdx.x * 128;
    const float*  Qb  = Q + (size_t)b * SS * DD;
    const __half* s1b = g_s1h + (size_t)b * DD * DD;
    float* smul = (float*)(sm + 2 * BUF2);

    const int ar = tid >> 1, aq0 = tid & 1;
    const int blr = tid >> 3, bq0 = tid & 7;
    const int wm = (wid >> 2) * 64, wn = (wid & 3) * 32;
    const int rowA = lane & 15, colA = (lane >> 4) << 3;
    const int rowB = lane & 15, colB = (lane >> 4) << 3;

    float acc[4][4][4];
#pragma unroll
    for (int i = 0; i < 4; i++)
#pragma unroll
        for (int j = 0; j < 4; j++)
#pragma unroll
            for (int t = 0; t < 4; t++) acc[i][j][t] = 0.f;

    const bool msk = is_masked(mask, b * SS + m0 + ar);
    float qss = 0.f;
    float4 ra[4]; uint2 rb[4];
    {
        const float* qr = Qb + (size_t)(m0 + ar) * DD;
#pragma unroll
        for (int j = 0; j < 4; j++) {
            ra[j] = *(const float4*)(qr + 4 * (aq0 + 2 * j));
            qss += ra[j].x*ra[j].x + ra[j].y*ra[j].y + ra[j].z*ra[j].z + ra[j].w*ra[j].w;
            if (msk) ra[j] = make_float4(1.f, 1.f, 1.f, 1.f);
            rb[j] = *(const uint2*)(s1b + (size_t)blr * DD + n0 + 4 * (bq0 + 8 * j));
        }
    }
    {
        char* Ah = sm; char* Bh = sm + A2SZ;
#pragma unroll
        for (int j = 0; j < 4; j++) {
            int off = ar * P2 + 8 * (aq0 + 2 * j);
            *(uint2*)(Ah + off) = make_uint2(pack_h(ra[j].x, ra[j].y),
                                             pack_h(ra[j].z, ra[j].w));
            int offb = blr * P1 + 8 * (bq0 + 8 * j);
            *(uint2*)(Bh + offb) = rb[j];
        }
    }
    __syncthreads();

    for (int c = 0; c < NCH2; c++) {
        if (c + 1 < NCH2) {
            int k0 = (c + 1) * 32;
            const float* qr = Qb + (size_t)(m0 + ar) * DD + k0;
#pragma unroll
            for (int j = 0; j < 4; j++) {
                ra[j] = *(const float4*)(qr + 4 * (aq0 + 2 * j));
                qss += ra[j].x*ra[j].x + ra[j].y*ra[j].y + ra[j].z*ra[j].z + ra[j].w*ra[j].w;
                if (msk) ra[j] = make_float4(1.f, 1.f, 1.f, 1.f);
                rb[j] = *(const uint2*)(s1b + (size_t)(k0 + blr) * DD + n0 + 4 * (bq0 + 8 * j));
            }
        }
        const uint32_t ub = sb + (uint32_t)(c & 1) * BUF2;
        const uint32_t uAh = ub, uBh = ub + A2SZ;
#pragma unroll
        for (int ks = 0; ks < 32; ks += 16) {
            uint32_t ah[4][4], bh[4][2];
#pragma unroll
            for (int mf = 0; mf < 4; mf++) {
                uint32_t a = (uint32_t)((wm + mf * 16 + rowA) * P2 + 2 * (ks + colA));
                ldsm_x4(ah[mf], uAh + a);
            }
#pragma unroll
            for (int nb = 0; nb < 2; nb++) {
                uint32_t a = (uint32_t)((ks + rowB) * P1 + 2 * (wn + nb * 16 + colB));
                ldsm_x4t(&bh[nb * 2][0], uBh + a);
            }
#pragma unroll
            for (int mi = 0; mi < 4; mi++)
#pragma unroll
                for (int ni = 0; ni < 4; ni++)
                    mma_f16(acc[mi][ni], ah[mi], bh[ni]);
        }
        if (c + 1 < NCH2) {
            char* bp = sm + ((c + 1) & 1) * BUF2;
            char* Ah = bp; char* Bh = bp + A2SZ;
#pragma unroll
            for (int j = 0; j < 4; j++) {
                int off = ar * P2 + 8 * (aq0 + 2 * j);
                *(uint2*)(Ah + off) = make_uint2(pack_h(ra[j].x, ra[j].y),
                                                 pack_h(ra[j].z, ra[j].w));
                int offb = blr * P1 + 8 * (bq0 + 8 * j);
                *(uint2*)(Bh + offb) = rb[j];
            }
        }
        __syncthreads();
    }

    qss += __shfl_xor_sync(0xFFFFFFFFu, qss, 1);
    if (aq0 == 0) smul[ar] = msk ? 0.0f : 1.0f / qss;
    __syncthreads();

    const float sc = 1.0f / 256.0f;
    const int r0 = lane >> 2, cp = (lane & 3) * 2;
#pragma unroll
    for (int mi = 0; mi < 4; mi++) {
        int m1 = m0 + wm + mi * 16 + r0;
        int m2 = m1 + 8;
        float mu1 = smul[m1 - m0], mu2 = smul[m2 - m0];
        float s1f = (mu1 == 0.0f) ? (NEGV * sc) : mu1 * sc;
        float s2f = (mu2 == 0.0f) ? (NEGV * sc) : mu2 * sc;
        float* o1 = Out + ((size_t)b * SS + m1) * DD;
        float* o2 = Out + ((size_t)b * SS + m2) * DD;
#pragma unroll
        for (int ni = 0; ni < 4; ni++) {
            int n = n0 + wn + ni * 8 + cp;
            *(float2*)(o1 + n) = make_float2(acc[mi][ni][0] * s1f, acc[mi][ni][1] * s1f);
            *(float2*)(o2 + n) = make_float2(acc[mi][ni][2] * s2f, acc[mi][ni][3] * s2f);
        }
    }
}

// ===========================================================================
extern "C" void kernel_launch(void* const* d_in, const int* in_sizes, int n_in,
                              void* d_out, int out_size) {
    const float* q    = (const float*)d_in[0];
    const float* k    = (const float*)d_in[1];
    const float* v    = (const float*)d_in[2];
    const void*  mask = d_in[3];
    float* out = (float*)d_out;

    const int SMEM_G1 = 2 * BUF1;          // 34816
    const int SMEM_G2 = 2 * BUF2 + 512;    // 38400
    cudaFuncSetAttribute(k_g1, cudaFuncAttributeMaxDynamicSharedMemorySize, SMEM_G1);
    cudaFuncSetAttribute(k_g2, cudaFuncAttributeMaxDynamicSharedMemorySize, SMEM_G2);

    k_knorm<<<NROWS / 8, 256>>>(k, (const unsigned int*)mask);
    k_g1<<<dim3(4, NSPLIT, BB), 256, SMEM_G1>>>(v);
    k_reduce<<<dim3(32, 8), 256>>>();
    k_g2<<<dim3(2, SS / 128, BB), 256, SMEM_G2>>>(q, mask, out);
}